// round 2
// baseline (speedup 1.0000x reference)
#include <cuda_runtime.h>
#include <math.h>

#define B_   64
#define C_   256
#define H_   56
#define W_   56
#define HW_  (H_*W_)          // 3136
#define NROWS (B_*C_)         // 16384
#define NV4   (HW_/4)         // 784
#define TOPK_ 38
#define HALF_ 2

__device__ float    g_sum[NROWS];
__device__ int      g_amax[NROWS];
__device__ float    g_lam[NROWS];
__device__ unsigned g_box[NROWS];

// ---------------- Kernel 1: per-row sum + first-index argmax ----------------
__global__ __launch_bounds__(256) void reduce_kernel(const float* __restrict__ x) {
    const int row = blockIdx.x;
    const float4* __restrict__ xr = (const float4*)(x + (size_t)row * HW_);

    float sum = 0.0f;
    float best = -INFINITY;
    int   bidx = 0;

    // strided float4 loop; indices strictly increase per thread, so ">" keeps first-max
    for (int i = threadIdx.x; i < NV4; i += 256) {
        float4 v = xr[i];
        sum += (v.x + v.y) + (v.z + v.w);
        int base = i * 4;
        if (v.x > best) { best = v.x; bidx = base; }
        if (v.y > best) { best = v.y; bidx = base + 1; }
        if (v.z > best) { best = v.z; bidx = base + 2; }
        if (v.w > best) { best = v.w; bidx = base + 3; }
    }

    // warp reduce (sum; argmax with min-index tie break)
    for (int off = 16; off > 0; off >>= 1) {
        float osum  = __shfl_down_sync(0xffffffffu, sum,  off);
        float obest = __shfl_down_sync(0xffffffffu, best, off);
        int   obidx = __shfl_down_sync(0xffffffffu, bidx, off);
        sum += osum;
        if (obest > best || (obest == best && obidx < bidx)) { best = obest; bidx = obidx; }
    }

    __shared__ float s_sum[8];
    __shared__ float s_best[8];
    __shared__ int   s_bidx[8];
    const int lane = threadIdx.x & 31;
    const int wid  = threadIdx.x >> 5;
    if (lane == 0) { s_sum[wid] = sum; s_best[wid] = best; s_bidx[wid] = bidx; }
    __syncthreads();

    if (wid == 0) {
        sum  = (lane < 8) ? s_sum[lane]  : 0.0f;
        best = (lane < 8) ? s_best[lane] : -INFINITY;
        bidx = (lane < 8) ? s_bidx[lane] : 0x7fffffff;
        for (int off = 4; off > 0; off >>= 1) {
            float osum  = __shfl_down_sync(0xffffffffu, sum,  off);
            float obest = __shfl_down_sync(0xffffffffu, best, off);
            int   obidx = __shfl_down_sync(0xffffffffu, bidx, off);
            sum += osum;
            if (obest > best || (obest == best && obidx < bidx)) { best = obest; bidx = obidx; }
        }
        if (lane == 0) { g_sum[row] = sum; g_amax[row] = bidx; }
    }
}

// ---------------- Kernel 2: SE block + exact top-k + per-row params ----------------
__global__ __launch_bounds__(256) void se_topk_kernel(const float* __restrict__ w1,
                                                      const float* __restrict__ w2) {
    const int b = blockIdx.x;
    const int c = threadIdx.x;   // 256 threads, one per channel

    __shared__ float pooled[C_];
    __shared__ float hidden[16];
    __shared__ float M[C_];

    pooled[c] = g_sum[b * C_ + c] * (1.0f / (float)HW_);
    __syncthreads();

    if (c < 16) {
        float acc = 0.0f;
        #pragma unroll 8
        for (int j = 0; j < C_; j++) acc += pooled[j] * w1[c * C_ + j];
        hidden[c] = fmaxf(acc, 0.0f);
    }
    __syncthreads();

    float acc = 0.0f;
    #pragma unroll
    for (int d = 0; d < 16; d++) acc += hidden[d] * w2[c * 16 + d];
    const float m = 1.0f / (1.0f + expf(-acc));
    M[c] = m;
    __syncthreads();

    // exact rank with lax.top_k tie semantics (lower index wins)
    int rank = 0;
    #pragma unroll 8
    for (int j = 0; j < C_; j++) {
        float mj = M[j];
        rank += (mj > m) || (mj == m && j < c);
    }
    const bool sel = (rank < TOPK_);

    const int idx = b * C_ + c;
    const int amax = g_amax[idx];
    const int mh = amax / W_;
    const int mw = amax - mh * W_;
    const int h1  = max(mh - HALF_, 0);
    const int h2  = min(mh + HALF_, H_ - 1);
    const int wb1 = max(mw - HALF_, 0);
    const int wb2 = min(mw + HALF_, W_ - 1);
    const int area = (h2 - h1 + 1) * (wb2 - wb1 + 1);

    g_lam[idx] = (float)HW_ / (float)(HW_ - area);
    g_box[idx] = sel ? ((1u << 31) | ((unsigned)h1 << 18) | ((unsigned)h2 << 12)
                        | ((unsigned)wb1 << 6) | (unsigned)wb2)
                     : 0u;
}

// ---------------- Kernel 3: apply mask ----------------
__global__ __launch_bounds__(256) void apply_kernel(const float* __restrict__ x,
                                                    float* __restrict__ out) {
    const int row = blockIdx.x;
    const unsigned box = g_box[row];
    const float lam = g_lam[row];
    const float4* __restrict__ xr = (const float4*)(x   + (size_t)row * HW_);
    float4* __restrict__       orr = (float4*)(out + (size_t)row * HW_);

    if (box == 0u) {
        // unselected: straight copy
        for (int i = threadIdx.x; i < NV4; i += 256) orr[i] = xr[i];
        return;
    }

    const int h1  = (box >> 18) & 63;
    const int h2  = (box >> 12) & 63;
    const int wb1 = (box >> 6)  & 63;
    const int wb2 = box & 63;

    for (int i = threadIdx.x; i < NV4; i += 256) {
        float4 v = xr[i];
        const int p = i * 4;        // W=56 divisible by 4 -> one float4 never crosses rows
        const int h = p / W_;
        const int w = p - h * W_;
        float4 o;
        if (h >= h1 && h <= h2) {
            o.x = (w     >= wb1 && w     <= wb2) ? 0.0f : v.x * lam;
            o.y = (w + 1 >= wb1 && w + 1 <= wb2) ? 0.0f : v.y * lam;
            o.z = (w + 2 >= wb1 && w + 2 <= wb2) ? 0.0f : v.z * lam;
            o.w = (w + 3 >= wb1 && w + 3 <= wb2) ? 0.0f : v.w * lam;
        } else {
            o.x = v.x * lam; o.y = v.y * lam; o.z = v.z * lam; o.w = v.w * lam;
        }
        orr[i] = o;
    }
}

extern "C" void kernel_launch(void* const* d_in, const int* in_sizes, int n_in,
                              void* d_out, int out_size) {
    const float* x  = (const float*)d_in[0];
    const float* w1 = (const float*)d_in[1];
    const float* w2 = (const float*)d_in[2];
    float* out = (float*)d_out;

    reduce_kernel<<<NROWS, 256>>>(x);
    se_topk_kernel<<<B_, 256>>>(w1, w2);
    apply_kernel<<<NROWS, 256>>>(x, out);
}

// round 6
// speedup vs baseline: 1.2085x; 1.2085x over previous
#include <cuda_runtime.h>
#include <math.h>

#define B_   64
#define C_   256
#define H_   56
#define W_   56
#define HW_  (H_*W_)          // 3136
#define NROWS (B_*C_)         // 16384
#define NV4   (HW_/4)         // 784
#define TOPK_ 38
#define HALF_ 2

__device__ float    g_sum[NROWS];
__device__ int      g_amax[NROWS];
__device__ float    g_lam[NROWS];
__device__ unsigned g_box[NROWS];

// ---------------- Kernel 1: per-row sum + first-index argmax ----------------
// 784 float4 per row, 256 threads: 3 unconditional + 1 predicated load per
// thread, all issued up front for maximum MLP.
__global__ __launch_bounds__(256) void reduce_kernel(const float* __restrict__ x) {
    const int row = blockIdx.x;
    const int tid = threadIdx.x;
    const float4* __restrict__ xr = (const float4*)(x + (size_t)row * HW_);

    const int  i0 = tid, i1 = tid + 256, i2 = tid + 512, i3 = tid + 768;
    const bool p3 = (i3 < NV4);   // only tid < 16

    float4 v0 = xr[i0];
    float4 v1 = xr[i1];
    float4 v2 = xr[i2];
    float4 v3 = p3 ? xr[i3] : make_float4(-INFINITY, -INFINITY, -INFINITY, -INFINITY);

    float sum = (v0.x + v0.y) + (v0.z + v0.w)
              + (v1.x + v1.y) + (v1.z + v1.w)
              + (v2.x + v2.y) + (v2.z + v2.w);
    if (p3) sum += (v3.x + v3.y) + (v3.z + v3.w);

    float best = -INFINITY;
    int   bidx = 0x7fffffff;
    // indices strictly increase v0 -> v3, so ">" keeps the first max
    {
        int base = i0 * 4;
        if (v0.x > best) { best = v0.x; bidx = base; }
        if (v0.y > best) { best = v0.y; bidx = base + 1; }
        if (v0.z > best) { best = v0.z; bidx = base + 2; }
        if (v0.w > best) { best = v0.w; bidx = base + 3; }
        base = i1 * 4;
        if (v1.x > best) { best = v1.x; bidx = base; }
        if (v1.y > best) { best = v1.y; bidx = base + 1; }
        if (v1.z > best) { best = v1.z; bidx = base + 2; }
        if (v1.w > best) { best = v1.w; bidx = base + 3; }
        base = i2 * 4;
        if (v2.x > best) { best = v2.x; bidx = base; }
        if (v2.y > best) { best = v2.y; bidx = base + 1; }
        if (v2.z > best) { best = v2.z; bidx = base + 2; }
        if (v2.w > best) { best = v2.w; bidx = base + 3; }
        base = i3 * 4;
        if (v3.x > best) { best = v3.x; bidx = base; }
        if (v3.y > best) { best = v3.y; bidx = base + 1; }
        if (v3.z > best) { best = v3.z; bidx = base + 2; }
        if (v3.w > best) { best = v3.w; bidx = base + 3; }
    }

    // warp reduce (sum; argmax with min-index tie break)
    for (int off = 16; off > 0; off >>= 1) {
        float osum  = __shfl_down_sync(0xffffffffu, sum,  off);
        float obest = __shfl_down_sync(0xffffffffu, best, off);
        int   obidx = __shfl_down_sync(0xffffffffu, bidx, off);
        sum += osum;
        if (obest > best || (obest == best && obidx < bidx)) { best = obest; bidx = obidx; }
    }

    __shared__ float s_sum[8];
    __shared__ float s_best[8];
    __shared__ int   s_bidx[8];
    const int lane = tid & 31;
    const int wid  = tid >> 5;
    if (lane == 0) { s_sum[wid] = sum; s_best[wid] = best; s_bidx[wid] = bidx; }
    __syncthreads();

    if (wid == 0) {
        sum  = (lane < 8) ? s_sum[lane]  : 0.0f;
        best = (lane < 8) ? s_best[lane] : -INFINITY;
        bidx = (lane < 8) ? s_bidx[lane] : 0x7fffffff;
        for (int off = 4; off > 0; off >>= 1) {
            float osum  = __shfl_down_sync(0xffffffffu, sum,  off);
            float obest = __shfl_down_sync(0xffffffffu, best, off);
            int   obidx = __shfl_down_sync(0xffffffffu, bidx, off);
            sum += osum;
            if (obest > best || (obest == best && obidx < bidx)) { best = obest; bidx = obidx; }
        }
        if (lane == 0) { g_sum[row] = sum; g_amax[row] = bidx; }
    }
}

// ---------------- Kernel 2: SE block + exact top-k + per-row params ----------------
__global__ __launch_bounds__(256) void se_topk_kernel(const float* __restrict__ w1,
                                                      const float* __restrict__ w2) {
    const int b = blockIdx.x;
    const int c = threadIdx.x;   // 256 threads, one per channel

    __shared__ float pooled[C_];
    __shared__ float hidden[16];
    __shared__ float M[C_];

    pooled[c] = g_sum[b * C_ + c] * (1.0f / (float)HW_);
    __syncthreads();

    if (c < 16) {
        float acc = 0.0f;
        #pragma unroll 8
        for (int j = 0; j < C_; j++) acc += pooled[j] * w1[c * C_ + j];
        hidden[c] = fmaxf(acc, 0.0f);
    }
    __syncthreads();

    float acc = 0.0f;
    #pragma unroll
    for (int d = 0; d < 16; d++) acc += hidden[d] * w2[c * 16 + d];
    const float m = 1.0f / (1.0f + expf(-acc));
    M[c] = m;
    __syncthreads();

    // exact rank with lax.top_k tie semantics (lower index wins)
    int rank = 0;
    #pragma unroll 8
    for (int j = 0; j < C_; j++) {
        float mj = M[j];
        rank += (mj > m) || (mj == m && j < c);
    }
    const bool sel = (rank < TOPK_);

    const int idx = b * C_ + c;
    const int amax = g_amax[idx];
    const int mh = amax / W_;
    const int mw = amax - mh * W_;
    const int h1  = max(mh - HALF_, 0);
    const int h2  = min(mh + HALF_, H_ - 1);
    const int wb1 = max(mw - HALF_, 0);
    const int wb2 = min(mw + HALF_, W_ - 1);
    const int area = (h2 - h1 + 1) * (wb2 - wb1 + 1);

    g_lam[idx] = (float)HW_ / (float)(HW_ - area);
    g_box[idx] = sel ? ((1u << 31) | ((unsigned)h1 << 18) | ((unsigned)h2 << 12)
                        | ((unsigned)wb1 << 6) | (unsigned)wb2)
                     : 0u;
}

// ---------------- Kernel 3: apply mask ----------------
// Rows processed in REVERSE order: the tail of x (most recently read by
// reduce_kernel) is still resident in L2, so apply's first blocks hit.
// x re-reads are dead after use (__ldcs) and output stores are streamed
// (__stcs) so they don't evict the cached portion of x.
__global__ __launch_bounds__(256) void apply_kernel(const float* __restrict__ x,
                                                    float* __restrict__ out) {
    const int row = (NROWS - 1) - blockIdx.x;
    const int tid = threadIdx.x;
    const unsigned box = g_box[row];
    const float lam = g_lam[row];
    const float4* __restrict__ xr  = (const float4*)(x   + (size_t)row * HW_);
    float4* __restrict__       orr = (float4*)(out + (size_t)row * HW_);

    const int  i0 = tid, i1 = tid + 256, i2 = tid + 512, i3 = tid + 768;
    const bool p3 = (i3 < NV4);

    float4 v0 = __ldcs(&xr[i0]);
    float4 v1 = __ldcs(&xr[i1]);
    float4 v2 = __ldcs(&xr[i2]);
    float4 v3 = p3 ? __ldcs(&xr[i3]) : make_float4(0.f, 0.f, 0.f, 0.f);

    if (box == 0u) {
        __stcs(&orr[i0], v0);
        __stcs(&orr[i1], v1);
        __stcs(&orr[i2], v2);
        if (p3) __stcs(&orr[i3], v3);
        return;
    }

    const int h1  = (box >> 18) & 63;
    const int h2  = (box >> 12) & 63;
    const int wb1 = (box >> 6)  & 63;
    const int wb2 = box & 63;

    #pragma unroll
    for (int k = 0; k < 4; k++) {
        const int  i = (k == 0) ? i0 : (k == 1) ? i1 : (k == 2) ? i2 : i3;
        if (k == 3 && !p3) break;
        float4 v = (k == 0) ? v0 : (k == 1) ? v1 : (k == 2) ? v2 : v3;
        const int p = i * 4;        // W=56 divisible by 4 -> float4 never crosses rows
        const int h = p / W_;
        const int w = p - h * W_;
        float4 o;
        if (h >= h1 && h <= h2) {
            o.x = (w     >= wb1 && w     <= wb2) ? 0.0f : v.x * lam;
            o.y = (w + 1 >= wb1 && w + 1 <= wb2) ? 0.0f : v.y * lam;
            o.z = (w + 2 >= wb1 && w + 2 <= wb2) ? 0.0f : v.z * lam;
            o.w = (w + 3 >= wb1 && w + 3 <= wb2) ? 0.0f : v.w * lam;
        } else {
            o.x = v.x * lam; o.y = v.y * lam; o.z = v.z * lam; o.w = v.w * lam;
        }
        __stcs(&orr[i], o);
    }
}

extern "C" void kernel_launch(void* const* d_in, const int* in_sizes, int n_in,
                              void* d_out, int out_size) {
    const float* x  = (const float*)d_in[0];
    const float* w1 = (const float*)d_in[1];
    const float* w2 = (const float*)d_in[2];
    float* out = (float*)d_out;

    reduce_kernel<<<NROWS, 256>>>(x);
    se_topk_kernel<<<B_, 256>>>(w1, w2);
    apply_kernel<<<NROWS, 256>>>(x, out);
}

// round 9
// speedup vs baseline: 1.3628x; 1.1277x over previous
#include <cuda_runtime.h>
#include <math.h>

#define B_   64
#define C_   256
#define H_   56
#define W_   56
#define HW_  (H_*W_)          // 3136
#define NROWS (B_*C_)         // 16384
#define NV4   (HW_/4)         // 784
#define TOPK_ 38
#define HALF_ 2
#define NSEL  (B_*TOPK_)      // 2432

__device__ float    g_sum[NROWS];
__device__ int      g_amax[NROWS];
__device__ float    g_lam[NROWS];
__device__ unsigned g_box[NROWS];
__device__ int      g_sel[NSEL];

// ---------------- Kernel 1: per-row sum + first-index argmax + copy ----------------
// While the row is in registers for the reduction, stream-copy it to out.
// Unselected rows (85.2%) are then already final; kernel 3 only rewrites
// the 38 selected rows per sample.
__global__ __launch_bounds__(256) void reduce_copy_kernel(const float* __restrict__ x,
                                                          float* __restrict__ out) {
    const int row = blockIdx.x;
    const int tid = threadIdx.x;
    const float4* __restrict__ xr  = (const float4*)(x   + (size_t)row * HW_);
    float4* __restrict__       orr = (float4*)(out + (size_t)row * HW_);

    const int  i0 = tid, i1 = tid + 256, i2 = tid + 512, i3 = tid + 768;
    const bool p3 = (i3 < NV4);   // only tid < 16

    float4 v0 = __ldcs(&xr[i0]);
    float4 v1 = __ldcs(&xr[i1]);
    float4 v2 = __ldcs(&xr[i2]);
    float4 v3 = p3 ? __ldcs(&xr[i3]) : make_float4(-INFINITY, -INFINITY, -INFINITY, -INFINITY);

    // speculative copy (overwritten later for selected rows)
    __stcs(&orr[i0], v0);
    __stcs(&orr[i1], v1);
    __stcs(&orr[i2], v2);
    if (p3) __stcs(&orr[i3], v3);

    float sum = (v0.x + v0.y) + (v0.z + v0.w)
              + (v1.x + v1.y) + (v1.z + v1.w)
              + (v2.x + v2.y) + (v2.z + v2.w);
    if (p3) sum += (v3.x + v3.y) + (v3.z + v3.w);

    float best = -INFINITY;
    int   bidx = 0x7fffffff;
    // indices strictly increase v0 -> v3, so ">" keeps the first max
    {
        int base = i0 * 4;
        if (v0.x > best) { best = v0.x; bidx = base; }
        if (v0.y > best) { best = v0.y; bidx = base + 1; }
        if (v0.z > best) { best = v0.z; bidx = base + 2; }
        if (v0.w > best) { best = v0.w; bidx = base + 3; }
        base = i1 * 4;
        if (v1.x > best) { best = v1.x; bidx = base; }
        if (v1.y > best) { best = v1.y; bidx = base + 1; }
        if (v1.z > best) { best = v1.z; bidx = base + 2; }
        if (v1.w > best) { best = v1.w; bidx = base + 3; }
        base = i2 * 4;
        if (v2.x > best) { best = v2.x; bidx = base; }
        if (v2.y > best) { best = v2.y; bidx = base + 1; }
        if (v2.z > best) { best = v2.z; bidx = base + 2; }
        if (v2.w > best) { best = v2.w; bidx = base + 3; }
        base = i3 * 4;
        if (v3.x > best) { best = v3.x; bidx = base; }
        if (v3.y > best) { best = v3.y; bidx = base + 1; }
        if (v3.z > best) { best = v3.z; bidx = base + 2; }
        if (v3.w > best) { best = v3.w; bidx = base + 3; }
    }

    // warp reduce (sum; argmax with min-index tie break)
    for (int off = 16; off > 0; off >>= 1) {
        float osum  = __shfl_down_sync(0xffffffffu, sum,  off);
        float obest = __shfl_down_sync(0xffffffffu, best, off);
        int   obidx = __shfl_down_sync(0xffffffffu, bidx, off);
        sum += osum;
        if (obest > best || (obest == best && obidx < bidx)) { best = obest; bidx = obidx; }
    }

    __shared__ float s_sum[8];
    __shared__ float s_best[8];
    __shared__ int   s_bidx[8];
    const int lane = tid & 31;
    const int wid  = tid >> 5;
    if (lane == 0) { s_sum[wid] = sum; s_best[wid] = best; s_bidx[wid] = bidx; }
    __syncthreads();

    if (wid == 0) {
        sum  = (lane < 8) ? s_sum[lane]  : 0.0f;
        best = (lane < 8) ? s_best[lane] : -INFINITY;
        bidx = (lane < 8) ? s_bidx[lane] : 0x7fffffff;
        for (int off = 4; off > 0; off >>= 1) {
            float osum  = __shfl_down_sync(0xffffffffu, sum,  off);
            float obest = __shfl_down_sync(0xffffffffu, best, off);
            int   obidx = __shfl_down_sync(0xffffffffu, bidx, off);
            sum += osum;
            if (obest > best || (obest == best && obidx < bidx)) { best = obest; bidx = obidx; }
        }
        if (lane == 0) { g_sum[row] = sum; g_amax[row] = bidx; }
    }
}

// ---------------- Kernel 2: SE block + exact top-k + per-row params + compact list ----------------
__global__ __launch_bounds__(256) void se_topk_kernel(const float* __restrict__ w1,
                                                      const float* __restrict__ w2) {
    const int b = blockIdx.x;
    const int c = threadIdx.x;   // 256 threads, one per channel

    __shared__ float pooled[C_];
    __shared__ float hidden[16];
    __shared__ float M[C_];

    pooled[c] = g_sum[b * C_ + c] * (1.0f / (float)HW_);
    __syncthreads();

    if (c < 16) {
        float acc = 0.0f;
        #pragma unroll 8
        for (int j = 0; j < C_; j++) acc += pooled[j] * w1[c * C_ + j];
        hidden[c] = fmaxf(acc, 0.0f);
    }
    __syncthreads();

    float acc = 0.0f;
    #pragma unroll
    for (int d = 0; d < 16; d++) acc += hidden[d] * w2[c * 16 + d];
    const float m = 1.0f / (1.0f + expf(-acc));
    M[c] = m;
    __syncthreads();

    // exact rank with lax.top_k tie semantics (lower index wins);
    // ranks are a permutation of 0..255 -> unique compact slot for rank < TOPK_
    int rank = 0;
    #pragma unroll 8
    for (int j = 0; j < C_; j++) {
        float mj = M[j];
        rank += (mj > m) || (mj == m && j < c);
    }

    const int idx = b * C_ + c;
    const int amax = g_amax[idx];
    const int mh = amax / W_;
    const int mw = amax - mh * W_;
    const int h1  = max(mh - HALF_, 0);
    const int h2  = min(mh + HALF_, H_ - 1);
    const int wb1 = max(mw - HALF_, 0);
    const int wb2 = min(mw + HALF_, W_ - 1);
    const int area = (h2 - h1 + 1) * (wb2 - wb1 + 1);

    g_lam[idx] = (float)HW_ / (float)(HW_ - area);
    g_box[idx] = ((unsigned)h1 << 18) | ((unsigned)h2 << 12)
               | ((unsigned)wb1 << 6) | (unsigned)wb2;

    if (rank < TOPK_) g_sel[b * TOPK_ + rank] = idx;
}

// ---------------- Kernel 3: fixup the 2432 selected rows ----------------
__global__ __launch_bounds__(256) void fixup_kernel(const float* __restrict__ x,
                                                    float* __restrict__ out) {
    const int row = g_sel[blockIdx.x];
    const int tid = threadIdx.x;
    const unsigned box = g_box[row];
    const float lam = g_lam[row];
    const float4* __restrict__ xr  = (const float4*)(x   + (size_t)row * HW_);
    float4* __restrict__       orr = (float4*)(out + (size_t)row * HW_);

    const int h1  = (box >> 18) & 63;
    const int h2  = (box >> 12) & 63;
    const int wb1 = (box >> 6)  & 63;
    const int wb2 = box & 63;

    const int  i0 = tid, i1 = tid + 256, i2 = tid + 512, i3 = tid + 768;
    const bool p3 = (i3 < NV4);

    float4 v0 = __ldcs(&xr[i0]);
    float4 v1 = __ldcs(&xr[i1]);
    float4 v2 = __ldcs(&xr[i2]);
    float4 v3 = p3 ? __ldcs(&xr[i3]) : make_float4(0.f, 0.f, 0.f, 0.f);

    #pragma unroll
    for (int k = 0; k < 4; k++) {
        if (k == 3 && !p3) break;
        const int i = (k == 0) ? i0 : (k == 1) ? i1 : (k == 2) ? i2 : i3;
        float4 v   = (k == 0) ? v0 : (k == 1) ? v1 : (k == 2) ? v2 : v3;
        const int p = i * 4;        // W=56 divisible by 4 -> float4 never crosses rows
        const int h = p / W_;
        const int w = p - h * W_;
        float4 o;
        if (h >= h1 && h <= h2) {
            o.x = (w     >= wb1 && w     <= wb2) ? 0.0f : v.x * lam;
            o.y = (w + 1 >= wb1 && w + 1 <= wb2) ? 0.0f : v.y * lam;
            o.z = (w + 2 >= wb1 && w + 2 <= wb2) ? 0.0f : v.z * lam;
            o.w = (w + 3 >= wb1 && w + 3 <= wb2) ? 0.0f : v.w * lam;
        } else {
            o.x = v.x * lam; o.y = v.y * lam; o.z = v.z * lam; o.w = v.w * lam;
        }
        __stcs(&orr[i], o);
    }
}

extern "C" void kernel_launch(void* const* d_in, const int* in_sizes, int n_in,
                              void* d_out, int out_size) {
    const float* x  = (const float*)d_in[0];
    const float* w1 = (const float*)d_in[1];
    const float* w2 = (const float*)d_in[2];
    float* out = (float*)d_out;

    reduce_copy_kernel<<<NROWS, 256>>>(x, out);
    se_topk_kernel<<<B_, 256>>>(w1, w2);
    fixup_kernel<<<NSEL, 256>>>(x, out);
}

// round 11
// speedup vs baseline: 1.4980x; 1.0991x over previous
#include <cuda_runtime.h>
#include <math.h>

#define B_   64
#define C_   256
#define H_   56
#define W_   56
#define HW_  (H_*W_)          // 3136
#define NROWS (B_*C_)         // 16384
#define NV4   (HW_/4)         // 784 = 24*32 + 16
#define TOPK_ 38
#define HALF_ 2
#define NSEL  (B_*TOPK_)      // 2432

__device__ float    g_sum[NROWS];
__device__ int      g_amax[NROWS];
__device__ float    g_lam[NROWS];
__device__ unsigned g_box[NROWS];
__device__ int      g_sel[NSEL];

// ---------------- Kernel 1: warp-per-row sum + first-index argmax + copy ----------------
// One warp owns one row: no smem, no block barrier, pure shuffle reduction.
// Loads batched 4-deep per iteration for explicit MLP.
__global__ __launch_bounds__(256) void reduce_copy_kernel(const float* __restrict__ x,
                                                          float* __restrict__ out) {
    const int lane = threadIdx.x & 31;
    const int row  = (blockIdx.x * 256 + threadIdx.x) >> 5;   // grid 2048 * 8 warps = 16384

    const float4* __restrict__ xr  = (const float4*)(x   + (size_t)row * HW_);
    float4* __restrict__       orr = (float4*)(out + (size_t)row * HW_);

    float sum  = 0.0f;
    float best = -INFINITY;
    int   bidx = 0x7fffffff;

    // 24 full warp-strides of 32 float4, batched 4 at a time
    #pragma unroll
    for (int k = 0; k < 24; k += 4) {
        const int ia = (k + 0) * 32 + lane;
        const int ib = (k + 1) * 32 + lane;
        const int ic = (k + 2) * 32 + lane;
        const int id = (k + 3) * 32 + lane;
        float4 va = __ldcs(&xr[ia]);
        float4 vb = __ldcs(&xr[ib]);
        float4 vc = __ldcs(&xr[ic]);
        float4 vd = __ldcs(&xr[id]);
        __stcs(&orr[ia], va);
        __stcs(&orr[ib], vb);
        __stcs(&orr[ic], vc);
        __stcs(&orr[id], vd);

        sum += (va.x + va.y) + (va.z + va.w)
             + (vb.x + vb.y) + (vb.z + vb.w)
             + (vc.x + vc.y) + (vc.z + vc.w)
             + (vd.x + vd.y) + (vd.z + vd.w);

        // per-lane indices strictly increase across k, so ">" keeps first max
        int base = ia * 4;
        if (va.x > best) { best = va.x; bidx = base; }
        if (va.y > best) { best = va.y; bidx = base + 1; }
        if (va.z > best) { best = va.z; bidx = base + 2; }
        if (va.w > best) { best = va.w; bidx = base + 3; }
        base = ib * 4;
        if (vb.x > best) { best = vb.x; bidx = base; }
        if (vb.y > best) { best = vb.y; bidx = base + 1; }
        if (vb.z > best) { best = vb.z; bidx = base + 2; }
        if (vb.w > best) { best = vb.w; bidx = base + 3; }
        base = ic * 4;
        if (vc.x > best) { best = vc.x; bidx = base; }
        if (vc.y > best) { best = vc.y; bidx = base + 1; }
        if (vc.z > best) { best = vc.z; bidx = base + 2; }
        if (vc.w > best) { best = vc.w; bidx = base + 3; }
        base = id * 4;
        if (vd.x > best) { best = vd.x; bidx = base; }
        if (vd.y > best) { best = vd.y; bidx = base + 1; }
        if (vd.z > best) { best = vd.z; bidx = base + 2; }
        if (vd.w > best) { best = vd.w; bidx = base + 3; }
    }

    // tail: 16 float4 (lanes 0..15)
    if (lane < 16) {
        const int it = 768 + lane;
        float4 v = __ldcs(&xr[it]);
        __stcs(&orr[it], v);
        sum += (v.x + v.y) + (v.z + v.w);
        const int base = it * 4;
        if (v.x > best) { best = v.x; bidx = base; }
        if (v.y > best) { best = v.y; bidx = base + 1; }
        if (v.z > best) { best = v.z; bidx = base + 2; }
        if (v.w > best) { best = v.w; bidx = base + 3; }
    }

    // warp reduce (sum; argmax with min-index tie break)
    #pragma unroll
    for (int off = 16; off > 0; off >>= 1) {
        float osum  = __shfl_down_sync(0xffffffffu, sum,  off);
        float obest = __shfl_down_sync(0xffffffffu, best, off);
        int   obidx = __shfl_down_sync(0xffffffffu, bidx, off);
        sum += osum;
        if (obest > best || (obest == best && obidx < bidx)) { best = obest; bidx = obidx; }
    }

    if (lane == 0) { g_sum[row] = sum; g_amax[row] = bidx; }
}

// ---------------- Kernel 2: SE block + exact top-k + per-row params + compact list ----------------
__global__ __launch_bounds__(256) void se_topk_kernel(const float* __restrict__ w1,
                                                      const float* __restrict__ w2) {
    const int b = blockIdx.x;
    const int c = threadIdx.x;   // 256 threads, one per channel

    __shared__ float pooled[C_];
    __shared__ float hidden[16];
    __shared__ float M[C_];

    pooled[c] = g_sum[b * C_ + c] * (1.0f / (float)HW_);
    __syncthreads();

    if (c < 16) {
        float acc = 0.0f;
        #pragma unroll 8
        for (int j = 0; j < C_; j++) acc += pooled[j] * w1[c * C_ + j];
        hidden[c] = fmaxf(acc, 0.0f);
    }
    __syncthreads();

    float acc = 0.0f;
    #pragma unroll
    for (int d = 0; d < 16; d++) acc += hidden[d] * w2[c * 16 + d];
    const float m = 1.0f / (1.0f + expf(-acc));
    M[c] = m;
    __syncthreads();

    // exact rank with lax.top_k tie semantics (lower index wins);
    // ranks are a permutation of 0..255 -> unique compact slot for rank < TOPK_
    int rank = 0;
    #pragma unroll 8
    for (int j = 0; j < C_; j++) {
        float mj = M[j];
        rank += (mj > m) || (mj == m && j < c);
    }

    const int idx = b * C_ + c;
    const int amax = g_amax[idx];
    const int mh = amax / W_;
    const int mw = amax - mh * W_;
    const int h1  = max(mh - HALF_, 0);
    const int h2  = min(mh + HALF_, H_ - 1);
    const int wb1 = max(mw - HALF_, 0);
    const int wb2 = min(mw + HALF_, W_ - 1);
    const int area = (h2 - h1 + 1) * (wb2 - wb1 + 1);

    g_lam[idx] = (float)HW_ / (float)(HW_ - area);
    g_box[idx] = ((unsigned)h1 << 18) | ((unsigned)h2 << 12)
               | ((unsigned)wb1 << 6) | (unsigned)wb2;

    if (rank < TOPK_) g_sel[b * TOPK_ + rank] = idx;
}

// ---------------- Kernel 3: fixup the 2432 selected rows ----------------
// Reverse order: the tail of x was streamed most recently by kernel 1 and may
// still be L2-resident; default-caching loads allow those hits.
__global__ __launch_bounds__(256) void fixup_kernel(const float* __restrict__ x,
                                                    float* __restrict__ out) {
    const int row = g_sel[(NSEL - 1) - blockIdx.x];
    const int tid = threadIdx.x;
    const unsigned box = g_box[row];
    const float lam = g_lam[row];
    const float4* __restrict__ xr  = (const float4*)(x   + (size_t)row * HW_);
    float4* __restrict__       orr = (float4*)(out + (size_t)row * HW_);

    const int h1  = (box >> 18) & 63;
    const int h2  = (box >> 12) & 63;
    const int wb1 = (box >> 6)  & 63;
    const int wb2 = box & 63;

    const int  i0 = tid, i1 = tid + 256, i2 = tid + 512, i3 = tid + 768;
    const bool p3 = (i3 < NV4);

    float4 v0 = xr[i0];
    float4 v1 = xr[i1];
    float4 v2 = xr[i2];
    float4 v3 = p3 ? xr[i3] : make_float4(0.f, 0.f, 0.f, 0.f);

    #pragma unroll
    for (int k = 0; k < 4; k++) {
        if (k == 3 && !p3) break;
        const int i = (k == 0) ? i0 : (k == 1) ? i1 : (k == 2) ? i2 : i3;
        float4 v   = (k == 0) ? v0 : (k == 1) ? v1 : (k == 2) ? v2 : v3;
        const int p = i * 4;        // W=56 divisible by 4 -> float4 never crosses rows
        const int h = p / W_;
        const int w = p - h * W_;
        float4 o;
        if (h >= h1 && h <= h2) {
            o.x = (w     >= wb1 && w     <= wb2) ? 0.0f : v.x * lam;
            o.y = (w + 1 >= wb1 && w + 1 <= wb2) ? 0.0f : v.y * lam;
            o.z = (w + 2 >= wb1 && w + 2 <= wb2) ? 0.0f : v.z * lam;
            o.w = (w + 3 >= wb1 && w + 3 <= wb2) ? 0.0f : v.w * lam;
        } else {
            o.x = v.x * lam; o.y = v.y * lam; o.z = v.z * lam; o.w = v.w * lam;
        }
        __stcs(&orr[i], o);
    }
}

extern "C" void kernel_launch(void* const* d_in, const int* in_sizes, int n_in,
                              void* d_out, int out_size) {
    const float* x  = (const float*)d_in[0];
    const float* w1 = (const float*)d_in[1];
    const float* w2 = (const float*)d_in[2];
    float* out = (float*)d_out;

    reduce_copy_kernel<<<NROWS / 8, 256>>>(x, out);
    se_topk_kernel<<<B_, 256>>>(w1, w2);
    fixup_kernel<<<NSEL, 256>>>(x, out);
}